// round 11
// baseline (speedup 1.0000x reference)
#include <cuda_runtime.h>
#include <cuda_bf16.h>
#include <cstdint>

#define C       128
#define ROWS    32768
#define KNBR    16

__device__ float g_y[ROWS * C];            // y = x @ W^T (16 MB)
__device__ uint4 g_wfrag[128 * 8 * 4];     // per-lane packed W frags (hi_b0,hi_b1,lo_b0,lo_b1)

// hi/lo bf16 split of a float pair, packed as bf16x2 words
__device__ __forceinline__ void hilo2(float a, float b, uint32_t& hi, uint32_t& lo) {
    __nv_bfloat162 h = __floats2bfloat162_rn(a, b);
    float ra = a - __bfloat162float(h.x);
    float rb = b - __bfloat162float(h.y);
    __nv_bfloat162 l = __floats2bfloat162_rn(ra, rb);
    hi = *reinterpret_cast<uint32_t*>(&h);
    lo = *reinterpret_cast<uint32_t*>(&l);
}

__device__ __forceinline__ void mma_bf16(float* c, const uint32_t* a, uint32_t b0, uint32_t b1) {
    asm volatile(
        "mma.sync.aligned.m16n8k16.row.col.f32.bf16.bf16.f32 "
        "{%0,%1,%2,%3}, {%4,%5,%6,%7}, {%8,%9}, {%0,%1,%2,%3};"
        : "+f"(c[0]), "+f"(c[1]), "+f"(c[2]), "+f"(c[3])
        : "r"(a[0]), "r"(a[1]), "r"(a[2]), "r"(a[3]), "r"(b0), "r"(b1));
}

// ============ Prologue: pack W[n][k] into MMA B-fragments (hi/lo) ============
// g_wfrag[(n*8 + ks)*4 + t] = {hi(W[n][16ks+2t],+1), hi(W[n][16ks+2t+8],+9), lo(...), lo(...)}
__global__ void pack_w_kernel(const float* __restrict__ W)
{
    const int idx = blockIdx.x * blockDim.x + threadIdx.x;   // 0..4095
    const int n  = idx >> 5;
    const int ks = (idx >> 2) & 7;
    const int t  = idx & 3;
    const int k0 = 16 * ks + 2 * t;
    const float* wr = W + (size_t)n * C;
    uint4 f;
    hilo2(wr[k0],     wr[k0 + 1], f.x, f.z);
    hilo2(wr[k0 + 8], wr[k0 + 9], f.y, f.w);
    g_wfrag[idx] = f;
}

// ============ GEMM: y = x @ W^T via mma.sync bf16x3 ============
// block = 128 thr (4 warps); each warp: 16 rows x 128 cols. grid = 512.
__global__ __launch_bounds__(128, 4)
void gemm_kernel(const float* __restrict__ x)
{
    const int lane = threadIdx.x & 31;
    const int wrp  = threadIdx.x >> 5;
    const int g    = lane >> 2;       // 0..7 : groupID
    const int t    = lane & 3;        // 0..3 : thread-in-group
    const int row0 = blockIdx.x * 64 + wrp * 16;

    float acc[16][4];
    #pragma unroll
    for (int nf = 0; nf < 16; nf++)
        #pragma unroll
        for (int q = 0; q < 4; q++) acc[nf][q] = 0.f;

    const float* xr0 = x + (size_t)(row0 + g) * C;       // row g
    const float* xr8 = x + (size_t)(row0 + g + 8) * C;   // row g+8

    #pragma unroll
    for (int ks = 0; ks < 8; ks++) {
        const int k0 = 16 * ks + 2 * t;
        float2 xa = *(const float2*)(xr0 + k0);          // A[g][2t..]       -> a0
        float2 xb = *(const float2*)(xr0 + k0 + 8);      // A[g][2t+8..]     -> a2
        float2 xc = *(const float2*)(xr8 + k0);          // A[g+8][2t..]     -> a1
        float2 xd = *(const float2*)(xr8 + k0 + 8);      // A[g+8][2t+8..]   -> a3

        uint32_t ahi[4], alo[4];
        hilo2(xa.x, xa.y, ahi[0], alo[0]);
        hilo2(xc.x, xc.y, ahi[1], alo[1]);
        hilo2(xb.x, xb.y, ahi[2], alo[2]);
        hilo2(xd.x, xd.y, ahi[3], alo[3]);

        // this thread's B column is n = 8*nf + g ; frag addr = ((8*nf+g)*8 + ks)*4 + t
        #pragma unroll
        for (int nf = 0; nf < 16; nf++) {
            uint4 f = g_wfrag[(size_t)(((8 * nf + g) * 8 + ks) << 2) + t];
            mma_bf16(acc[nf], ahi, f.x, f.y);            // hi*hi
            mma_bf16(acc[nf], ahi, f.z, f.w);            // hi*lo
            mma_bf16(acc[nf], alo, f.x, f.y);            // lo*hi
        }
    }

    // store: c0,c1 -> y[row0+g][8nf+2t, +1]; c2,c3 -> row+8
    float* y0 = g_y + (size_t)(row0 + g) * C + 2 * t;
    float* y8 = g_y + (size_t)(row0 + g + 8) * C + 2 * t;
    #pragma unroll
    for (int nf = 0; nf < 16; nf++) {
        *(float2*)(y0 + 8 * nf) = make_float2(acc[nf][0], acc[nf][1]);
        *(float2*)(y8 + 8 * nf) = make_float2(acc[nf][2], acc[nf][3]);
    }
}

// ============ Gather: out = relu((1+eps)*y_self + sum y_j + b) ============
__global__ __launch_bounds__(256)
void gather_kernel(const void* __restrict__ ei_raw,
                   const float* __restrict__ bias,
                   const float* __restrict__ epsp,
                   float* __restrict__ out)
{
    // dtype sniff: int64 (odd 32-bit words all 0 for idx<8192) vs int32
    const int* w32 = (const int*)ei_raw;
    int orv = 0;
    #pragma unroll
    for (int tt = 0; tt < 16; tt++) orv |= w32[tt * 8192 + 1];
    const bool is64 = (orv == 0);
    const long long* w64 = (const long long*)ei_raw;

    const int tid = threadIdx.x;
    const int row = blockIdx.x * 32 + (tid >> 3);
    const int p   = tid & 7;
    const int bbase = (row >> 13) << 13;       // b * 8192
    const float oe = 1.0f + epsp[0];

    int idxs[KNBR];
    if (!is64) {
        const int4* ip = (const int4*)(w32 + (size_t)row * KNBR);
        #pragma unroll
        for (int q = 0; q < 4; q++) {
            int4 v = ip[q];
            idxs[4*q+0] = v.x; idxs[4*q+1] = v.y;
            idxs[4*q+2] = v.z; idxs[4*q+3] = v.w;
        }
    } else {
        #pragma unroll
        for (int k = 0; k < KNBR; k++)
            idxs[k] = (int)w64[(size_t)row * KNBR + k];
    }
    #pragma unroll
    for (int k = 0; k < KNBR; k++)
        idxs[k] = (bbase + idxs[k]) << 7;      // float offset into g_y

    const float* ys = g_y + ((size_t)row << 7) + 4 * p;
    float4 acc[4];
    #pragma unroll
    for (int j = 0; j < 4; j++) {
        float4 v = *(const float4*)(ys + 32 * j);
        acc[j].x = v.x * oe; acc[j].y = v.y * oe;
        acc[j].z = v.z * oe; acc[j].w = v.w * oe;
    }
    #pragma unroll 4
    for (int k = 0; k < KNBR; k++) {
        const float* yn = g_y + idxs[k] + 4 * p;
        #pragma unroll
        for (int j = 0; j < 4; j++) {
            float4 v = *(const float4*)(yn + 32 * j);
            acc[j].x += v.x; acc[j].y += v.y;
            acc[j].z += v.z; acc[j].w += v.w;
        }
    }
    #pragma unroll
    for (int j = 0; j < 4; j++) {
        float4 b = *(const float4*)(bias + 32 * j + 4 * p);
        float4 o;
        o.x = fmaxf(acc[j].x + b.x, 0.f);
        o.y = fmaxf(acc[j].y + b.y, 0.f);
        o.z = fmaxf(acc[j].z + b.z, 0.f);
        o.w = fmaxf(acc[j].w + b.w, 0.f);
        *(float4*)(out + ((size_t)row << 7) + 32 * j + 4 * p) = o;
    }
}

extern "C" void kernel_launch(void* const* d_in, const int* in_sizes, int n_in,
                              void* d_out, int out_size)
{
    const float* x    = (const float*)d_in[0];
    const void*  ei   = d_in[1];
    const float* W    = (const float*)d_in[2];
    const float* bias = (const float*)d_in[3];
    const float* eps  = (const float*)d_in[4];
    float*       out  = (float*)d_out;

    pack_w_kernel<<<4, 1024>>>(W);                          // W -> MMA frags (hi/lo)
    gemm_kernel<<<ROWS / 64, 128>>>(x);                     // y = x @ W^T (HMMA bf16x3)
    gather_kernel<<<ROWS / 32, 256>>>(ei, bias, eps, out);  // aggregate + relu
}

// round 12
// speedup vs baseline: 1.3609x; 1.3609x over previous
#include <cuda_runtime.h>
#include <cuda_bf16.h>
#include <cstdint>

#define KNBR     16
#define C        128
#define ROWS     32768
#define TM       32              // rows per stage
#define THREADS  256             // warps 0-3 producer, 4-7 consumer
#define NTILES   (ROWS / TM)     // 1024
#define GRID     304             // 2 blocks/SM

// smem layout (bytes):
//   [0, 65536)          : sWf  — 4096 uint4 W-fragments, [ks][n][t]
//   [65536, 65536+2*17408) : 2 stages x (h_hi 8704 B + h_lo 8704 B)
#define SWF_BYTES   65536
#define HSTRIDE_W   68           // u32 words per h row (136 bf16 = 272 B)
#define STAGE_U32   (TM * HSTRIDE_W)          // 2176 u32 per hi or lo array
#define STAGE_BYTES (2 * STAGE_U32 * 4)       // 17408
#define SMEM_BYTES  (SWF_BYTES + 2 * STAGE_BYTES)   // 100352

typedef unsigned long long u64;

__device__ __forceinline__ u64 add2(u64 a, u64 b) {
    u64 d; asm("add.rn.f32x2 %0, %1, %2;" : "=l"(d) : "l"(a), "l"(b)); return d;
}
__device__ __forceinline__ u64 mul2(u64 a, u64 b) {
    u64 d; asm("mul.rn.f32x2 %0, %1, %2;" : "=l"(d) : "l"(a), "l"(b)); return d;
}
__device__ __forceinline__ u64 rep2(float v) {
    u64 d; asm("mov.b64 %0, {%1, %1};" : "=l"(d) : "f"(v)); return d;
}
__device__ __forceinline__ float2 unpack2(u64 v) {
    float2 r; asm("mov.b64 {%0, %1}, %2;" : "=f"(r.x), "=f"(r.y) : "l"(v)); return r;
}
__device__ __forceinline__ void hilo2(float a, float b, uint32_t& hi, uint32_t& lo) {
    __nv_bfloat162 h = __floats2bfloat162_rn(a, b);
    float ra = a - __bfloat162float(h.x);
    float rb = b - __bfloat162float(h.y);
    __nv_bfloat162 l = __floats2bfloat162_rn(ra, rb);
    hi = *reinterpret_cast<uint32_t*>(&h);
    lo = *reinterpret_cast<uint32_t*>(&l);
}
__device__ __forceinline__ void mma_bf16(float* c, const uint32_t* a, uint32_t b0, uint32_t b1) {
    asm volatile(
        "mma.sync.aligned.m16n8k16.row.col.f32.bf16.bf16.f32 "
        "{%0,%1,%2,%3}, {%4,%5,%6,%7}, {%8,%9}, {%0,%1,%2,%3};"
        : "+f"(c[0]), "+f"(c[1]), "+f"(c[2]), "+f"(c[3])
        : "r"(a[0]), "r"(a[1]), "r"(a[2]), "r"(a[3]), "r"(b0), "r"(b1));
}
__device__ __forceinline__ void ldsm4(uint32_t* r, uint32_t addr) {
    asm volatile("ldmatrix.sync.aligned.m8n8.x4.shared.b16 {%0,%1,%2,%3}, [%4];"
        : "=r"(r[0]), "=r"(r[1]), "=r"(r[2]), "=r"(r[3]) : "r"(addr));
}
__device__ __forceinline__ uint32_t smem_u32p(const void* p) {
    uint32_t a;
    asm("{ .reg .u64 t; cvta.to.shared.u64 t, %1; cvt.u32.u64 %0, t; }" : "=r"(a) : "l"(p));
    return a;
}
__device__ __forceinline__ void bar_sync(int id) {
    asm volatile("bar.sync %0, 256;" :: "r"(id) : "memory");
}
__device__ __forceinline__ void bar_arrive(int id) {
    asm volatile("bar.arrive %0, 256;" :: "r"(id) : "memory");
}

__global__ __launch_bounds__(THREADS, 2)
void gin_fused_kernel(const float* __restrict__ x,
                      const void* __restrict__ ei_raw,
                      const float* __restrict__ W,
                      const float* __restrict__ bias,
                      const float* __restrict__ epsp,
                      float* __restrict__ out)
{
    extern __shared__ char smem[];
    uint4*    sWf  = (uint4*)smem;                         // [ks][n][t]
    uint32_t* hbuf = (uint32_t*)(smem + SWF_BYTES);        // 2 stages x (hi | lo)

    const int tid = threadIdx.x;

    // ---------- dtype sniff: int64 (odd words all 0) vs int32 ----------
    const int* w32 = (const int*)ei_raw;
    int orv = 0;
    #pragma unroll
    for (int t = 0; t < 64; t++) orv |= w32[t * 8192 + 1];
    const bool is64 = (orv == 0);
    const long long* w64 = (const long long*)ei_raw;

    // ---------- build W fragments in smem: frag[ks*512 + n*4 + t] ----------
    // frag = {hi(W[n][k0],k0+1), hi(W[n][k0+8],k0+9), lo(..), lo(..)}, k0=16ks+2t
    #pragma unroll
    for (int i = 0; i < 16; i++) {
        const int idx = tid + 256 * i;
        const int ks  = idx >> 9;
        const int n   = (idx >> 2) & 127;
        const int t   = idx & 3;
        const int k0  = 16 * ks + 2 * t;
        const float* wr = W + (size_t)n * C;
        float2 wa = *(const float2*)(wr + k0);
        float2 wb = *(const float2*)(wr + k0 + 8);
        uint4 f;
        hilo2(wa.x, wa.y, f.x, f.z);
        hilo2(wb.x, wb.y, f.y, f.w);
        sWf[idx] = f;
    }
    __syncthreads();

    const float oe  = 1.0f + epsp[0];
    const u64   oe2 = rep2(oe);

    if (tid < 128) {
        // =================== PRODUCER: warps 0-3 ===================
        const int rl = tid >> 3;        // 0..15 : rows rl and rl+16
        const int p  = tid & 7;         // 16B slice of every 128B line

        int iter = 0;
        for (int tile = blockIdx.x; tile < NTILES; tile += GRID, iter++) {
            const int s = iter & 1;
            const int row0 = tile * TM;
            uint32_t* shi = hbuf + s * (2 * STAGE_U32);
            uint32_t* slo = shi + STAGE_U32;

            if (iter >= 2) bar_sync(3 + s);      // stage s consumed?

            #pragma unroll
            for (int hh = 0; hh < 2; hh++) {
                const int lrow = rl + 16 * hh;
                const int row  = row0 + lrow;
                const int bbase = (row >> 13) << 13;   // b * 8192

                int idxs[KNBR];
                if (!is64) {
                    const int4* ip = (const int4*)(w32 + (size_t)row * KNBR);
                    #pragma unroll
                    for (int q = 0; q < 4; q++) {
                        int4 v = ip[q];
                        idxs[4*q+0] = v.x; idxs[4*q+1] = v.y;
                        idxs[4*q+2] = v.z; idxs[4*q+3] = v.w;
                    }
                } else {
                    #pragma unroll
                    for (int k = 0; k < KNBR; k++)
                        idxs[k] = (int)w64[(size_t)row * KNBR + k];
                }
                #pragma unroll
                for (int k = 0; k < KNBR; k++)
                    idxs[k] = (bbase + idxs[k]) << 7;

                const float* xs = x + ((size_t)row << 7) + 4 * p;
                u64 a[8];
                #pragma unroll
                for (int j = 0; j < 4; j++) {
                    ulonglong2 v = *(const ulonglong2*)(xs + 32 * j);
                    a[2*j]   = mul2(v.x, oe2);
                    a[2*j+1] = mul2(v.y, oe2);
                }
                #pragma unroll 4
                for (int k = 0; k < KNBR; k++) {
                    const float* xn = x + idxs[k] + 4 * p;
                    #pragma unroll
                    for (int j = 0; j < 4; j++) {
                        ulonglong2 v = *(const ulonglong2*)(xn + 32 * j);
                        a[2*j]   = add2(a[2*j],   v.x);
                        a[2*j+1] = add2(a[2*j+1], v.y);
                    }
                }
                // convert to bf16 hi/lo and store (channels 32j+4p..+3)
                #pragma unroll
                for (int j = 0; j < 4; j++) {
                    float2 f0 = unpack2(a[2*j]);
                    float2 f1 = unpack2(a[2*j+1]);
                    uint32_t h0, l0, h1, l1;
                    hilo2(f0.x, f0.y, h0, l0);
                    hilo2(f1.x, f1.y, h1, l1);
                    const int wi = lrow * HSTRIDE_W + 16 * j + 2 * p;   // even
                    *(uint2*)(shi + wi) = make_uint2(h0, h1);
                    *(uint2*)(slo + wi) = make_uint2(l0, l1);
                }
            }
            bar_arrive(1 + s);           // stage s full
        }
    } else {
        // =================== CONSUMER: warps 4-7 ===================
        // warp w: n in [32w, 32w+32), rows: both 16-row m-tiles of the stage.
        const int ct   = tid - 128;
        const int w    = ct >> 5;
        const int lane = ct & 31;
        const int g    = lane >> 2;
        const int t    = lane & 3;

        // ldmatrix per-lane byte offset (row, col-half), ks-invariant part
        const int lrow = (lane & 15);               // + 16*mt
        const int choff = ((lane >> 4) << 4);       // bytes: +8 bf16 for lanes 16-31
        const uint32_t hbase = smem_u32p(hbuf);

        float2 bb[4];
        #pragma unroll
        for (int nfp = 0; nfp < 4; nfp++)
            bb[nfp] = *(const float2*)(bias + 32 * w + 8 * nfp + 2 * t);

        int iter = 0;
        for (int tile = blockIdx.x; tile < NTILES; tile += GRID, iter++) {
            const int s = iter & 1;
            const int row0 = tile * TM;
            const uint32_t hi0 = hbase + s * (2 * STAGE_U32 * 4);
            const uint32_t lo0 = hi0 + STAGE_U32 * 4;

            bar_sync(1 + s);             // wait stage full

            float acc[2][4][4];          // [mt][nf'][c]
            #pragma unroll
            for (int mt = 0; mt < 2; mt++)
                #pragma unroll
                for (int nfp = 0; nfp < 4; nfp++)
                    #pragma unroll
                    for (int q = 0; q < 4; q++) acc[mt][nfp][q] = 0.f;

            #pragma unroll
            for (int ks = 0; ks < 8; ks++) {
                uint32_t ahi[2][4], alo[2][4];
                #pragma unroll
                for (int mt = 0; mt < 2; mt++) {
                    const uint32_t boff =
                        (uint32_t)((16 * mt + lrow) * 272) + choff + 32 * ks;
                    ldsm4(ahi[mt], hi0 + boff);
                    ldsm4(alo[mt], lo0 + boff);
                }
                #pragma unroll
                for (int nfp = 0; nfp < 4; nfp++) {
                    uint4 f = sWf[ks * 512 + (32 * w + 8 * nfp + g) * 4 + t];
                    #pragma unroll
                    for (int mt = 0; mt < 2; mt++) {
                        mma_bf16(acc[mt][nfp], ahi[mt], f.x, f.y);   // hi*hi
                        mma_bf16(acc[mt][nfp], ahi[mt], f.z, f.w);   // hi*lo
                        mma_bf16(acc[mt][nfp], alo[mt], f.x, f.y);   // lo*hi
                    }
                }
            }
            bar_arrive(3 + s);           // stage free (acc in regs)

            // epilogue: c0,c1 -> row0+16mt+g ; c2,c3 -> +8 ; cols 32w+8nf'+2t
            #pragma unroll
            for (int mt = 0; mt < 2; mt++) {
                const int r0 = row0 + 16 * mt + g;
                #pragma unroll
                for (int nfp = 0; nfp < 4; nfp++) {
                    const int col = 32 * w + 8 * nfp + 2 * t;
                    float2 o0, o1;
                    o0.x = fmaxf(acc[mt][nfp][0] + bb[nfp].x, 0.f);
                    o0.y = fmaxf(acc[mt][nfp][1] + bb[nfp].y, 0.f);
                    o1.x = fmaxf(acc[mt][nfp][2] + bb[nfp].x, 0.f);
                    o1.y = fmaxf(acc[mt][nfp][3] + bb[nfp].y, 0.f);
                    *(float2*)(out + (size_t)r0 * C + col)       = o0;
                    *(float2*)(out + (size_t)(r0 + 8) * C + col) = o1;
                }
            }
        }
    }
}

extern "C" void kernel_launch(void* const* d_in, const int* in_sizes, int n_in,
                              void* d_out, int out_size)
{
    const float* x    = (const float*)d_in[0];
    const void*  ei   = d_in[1];
    const float* W    = (const float*)d_in[2];
    const float* bias = (const float*)d_in[3];
    const float* eps  = (const float*)d_in[4];
    float*       out  = (float*)d_out;

    cudaFuncSetAttribute(gin_fused_kernel,
                         cudaFuncAttributeMaxDynamicSharedMemorySize, SMEM_BYTES);

    gin_fused_kernel<<<GRID, THREADS, SMEM_BYTES>>>(x, ei, W, bias, eps, out);
}

// round 13
// speedup vs baseline: 1.4427x; 1.0601x over previous
#include <cuda_runtime.h>
#include <cuda_bf16.h>
#include <cstdint>

#define KNBR     16
#define C        128
#define ROWS     32768
#define TM       32              // rows per stage
#define THREADS  384             // warps 0-7 producer, 8-11 consumer
#define NTILES   (ROWS / TM)     // 1024
#define GRID     304             // 2 blocks/SM

// smem layout (bytes):
//   [0, 65536)             : sWf  — 4096 uint4 W-fragments, [ks][n][t]
//   [65536, +2*17408)      : 2 stages x (h_hi 8704 B + h_lo 8704 B)
#define SWF_BYTES   65536
#define HSTRIDE_W   68           // u32 words per h row (136 bf16 = 272 B)
#define STAGE_U32   (TM * HSTRIDE_W)          // 2176 u32 per hi or lo array
#define STAGE_BYTES (2 * STAGE_U32 * 4)       // 17408
#define SMEM_BYTES  (SWF_BYTES + 2 * STAGE_BYTES)   // 100352

typedef unsigned long long u64;

__device__ __forceinline__ u64 add2(u64 a, u64 b) {
    u64 d; asm("add.rn.f32x2 %0, %1, %2;" : "=l"(d) : "l"(a), "l"(b)); return d;
}
__device__ __forceinline__ u64 mul2(u64 a, u64 b) {
    u64 d; asm("mul.rn.f32x2 %0, %1, %2;" : "=l"(d) : "l"(a), "l"(b)); return d;
}
__device__ __forceinline__ u64 rep2(float v) {
    u64 d; asm("mov.b64 %0, {%1, %1};" : "=l"(d) : "f"(v)); return d;
}
__device__ __forceinline__ float2 unpack2(u64 v) {
    float2 r; asm("mov.b64 {%0, %1}, %2;" : "=f"(r.x), "=f"(r.y) : "l"(v)); return r;
}
__device__ __forceinline__ void hilo2(float a, float b, uint32_t& hi, uint32_t& lo) {
    __nv_bfloat162 h = __floats2bfloat162_rn(a, b);
    float ra = a - __bfloat162float(h.x);
    float rb = b - __bfloat162float(h.y);
    __nv_bfloat162 l = __floats2bfloat162_rn(ra, rb);
    hi = *reinterpret_cast<uint32_t*>(&h);
    lo = *reinterpret_cast<uint32_t*>(&l);
}
__device__ __forceinline__ void mma_bf16(float* c, const uint32_t* a, uint32_t b0, uint32_t b1) {
    asm volatile(
        "mma.sync.aligned.m16n8k16.row.col.f32.bf16.bf16.f32 "
        "{%0,%1,%2,%3}, {%4,%5,%6,%7}, {%8,%9}, {%0,%1,%2,%3};"
        : "+f"(c[0]), "+f"(c[1]), "+f"(c[2]), "+f"(c[3])
        : "r"(a[0]), "r"(a[1]), "r"(a[2]), "r"(a[3]), "r"(b0), "r"(b1));
}
__device__ __forceinline__ void ldsm4(uint32_t* r, uint32_t addr) {
    asm volatile("ldmatrix.sync.aligned.m8n8.x4.shared.b16 {%0,%1,%2,%3}, [%4];"
        : "=r"(r[0]), "=r"(r[1]), "=r"(r[2]), "=r"(r[3]) : "r"(addr));
}
__device__ __forceinline__ uint32_t smem_u32p(const void* p) {
    uint32_t a;
    asm("{ .reg .u64 t; cvta.to.shared.u64 t, %1; cvt.u32.u64 %0, t; }" : "=r"(a) : "l"(p));
    return a;
}
__device__ __forceinline__ void bar_sync(int id) {
    asm volatile("bar.sync %0, 384;" :: "r"(id) : "memory");
}
__device__ __forceinline__ void bar_arrive(int id) {
    asm volatile("bar.arrive %0, 384;" :: "r"(id) : "memory");
}

__global__ __launch_bounds__(THREADS, 2)
void gin_fused_kernel(const float* __restrict__ x,
                      const void* __restrict__ ei_raw,
                      const float* __restrict__ W,
                      const float* __restrict__ bias,
                      const float* __restrict__ epsp,
                      float* __restrict__ out)
{
    extern __shared__ char smem[];
    uint4*    sWf  = (uint4*)smem;                         // [ks][n][t]
    uint32_t* hbuf = (uint32_t*)(smem + SWF_BYTES);        // 2 stages x (hi | lo)

    const int tid = threadIdx.x;

    // ---------- dtype sniff: int64 (odd words all 0) vs int32 ----------
    const int* w32 = (const int*)ei_raw;
    int orv = 0;
    #pragma unroll
    for (int t = 0; t < 64; t++) orv |= w32[t * 8192 + 1];
    const bool is64 = (orv == 0);
    const long long* w64 = (const long long*)ei_raw;

    // ---------- build W fragments in smem: frag[ks*512 + n*4 + t] ----------
    for (int idx = tid; idx < 4096; idx += THREADS) {
        const int ks = idx >> 9;
        const int n  = (idx >> 2) & 127;
        const int t  = idx & 3;
        const int k0 = 16 * ks + 2 * t;
        const float* wr = W + (size_t)n * C;
        float2 wa = *(const float2*)(wr + k0);
        float2 wb = *(const float2*)(wr + k0 + 8);
        uint4 f;
        hilo2(wa.x, wa.y, f.x, f.z);
        hilo2(wb.x, wb.y, f.y, f.w);
        sWf[idx] = f;
    }
    __syncthreads();

    const float oe  = 1.0f + epsp[0];
    const u64   oe2 = rep2(oe);

    if (tid < 256) {
        // =================== PRODUCER: warps 0-7 (one row slice per thread) ===================
        const int lrow = tid >> 3;        // 0..31 : row within tile
        const int p    = tid & 7;         // 16B slice of every 128B line

        int iter = 0;
        for (int tile = blockIdx.x; tile < NTILES; tile += GRID, iter++) {
            const int s = iter & 1;
            const int row = tile * TM + lrow;
            const int bbase = (row >> 13) << 13;   // b * 8192
            uint32_t* shi = hbuf + s * (2 * STAGE_U32);
            uint32_t* slo = shi + STAGE_U32;

            if (iter >= 2) bar_sync(3 + s);        // stage s consumed?

            int idxs[KNBR];
            if (!is64) {
                const int4* ip = (const int4*)(w32 + (size_t)row * KNBR);
                #pragma unroll
                for (int q = 0; q < 4; q++) {
                    int4 v = ip[q];
                    idxs[4*q+0] = v.x; idxs[4*q+1] = v.y;
                    idxs[4*q+2] = v.z; idxs[4*q+3] = v.w;
                }
            } else {
                #pragma unroll
                for (int k = 0; k < KNBR; k++)
                    idxs[k] = (int)w64[(size_t)row * KNBR + k];
            }
            #pragma unroll
            for (int k = 0; k < KNBR; k++)
                idxs[k] = (bbase + idxs[k]) << 7;

            const float* xs = x + ((size_t)row << 7) + 4 * p;
            u64 a[8];
            #pragma unroll
            for (int j = 0; j < 4; j++) {
                ulonglong2 v = *(const ulonglong2*)(xs + 32 * j);
                a[2*j]   = mul2(v.x, oe2);
                a[2*j+1] = mul2(v.y, oe2);
            }
            #pragma unroll 4
            for (int k = 0; k < KNBR; k++) {
                const float* xn = x + idxs[k] + 4 * p;
                #pragma unroll
                for (int j = 0; j < 4; j++) {
                    ulonglong2 v = *(const ulonglong2*)(xn + 32 * j);
                    a[2*j]   = add2(a[2*j],   v.x);
                    a[2*j+1] = add2(a[2*j+1], v.y);
                }
            }
            // convert to bf16 hi/lo and store (channels 32j+4p..+3)
            #pragma unroll
            for (int j = 0; j < 4; j++) {
                float2 f0 = unpack2(a[2*j]);
                float2 f1 = unpack2(a[2*j+1]);
                uint32_t h0, l0, h1, l1;
                hilo2(f0.x, f0.y, h0, l0);
                hilo2(f1.x, f1.y, h1, l1);
                const int wi = lrow * HSTRIDE_W + 16 * j + 2 * p;
                *(uint2*)(shi + wi) = make_uint2(h0, h1);
                *(uint2*)(slo + wi) = make_uint2(l0, l1);
            }
            bar_arrive(1 + s);           // stage s full
        }
    } else {
        // =================== CONSUMER: warps 8-11 ===================
        // warp w: n in [32w, 32w+32), both 16-row m-tiles of the stage.
        const int ct   = tid - 256;
        const int w    = ct >> 5;
        const int lane = ct & 31;
        const int g    = lane >> 2;
        const int t    = lane & 3;

        const int lrow  = (lane & 15);               // + 16*mt
        const int choff = ((lane >> 4) << 4);        // +8 bf16 for lanes 16-31
        const uint32_t hbase = smem_u32p(hbuf);

        float2 bb[4];
        #pragma unroll
        for (int nfp = 0; nfp < 4; nfp++)
            bb[nfp] = *(const float2*)(bias + 32 * w + 8 * nfp + 2 * t);

        int iter = 0;
        for (int tile = blockIdx.x; tile < NTILES; tile += GRID, iter++) {
            const int s = iter & 1;
            const int row0 = tile * TM;
            const uint32_t hi0 = hbase + s * (2 * STAGE_U32 * 4);
            const uint32_t lo0 = hi0 + STAGE_U32 * 4;

            bar_sync(1 + s);             // wait stage full

            float acc[2][4][4];          // [mt][nf'][c]
            #pragma unroll
            for (int mt = 0; mt < 2; mt++)
                #pragma unroll
                for (int nfp = 0; nfp < 4; nfp++)
                    #pragma unroll
                    for (int q = 0; q < 4; q++) acc[mt][nfp][q] = 0.f;

            #pragma unroll
            for (int ks = 0; ks < 8; ks++) {
                uint32_t ahi[2][4], alo[2][4];
                #pragma unroll
                for (int mt = 0; mt < 2; mt++) {
                    const uint32_t boff =
                        (uint32_t)((16 * mt + lrow) * 272) + choff + 32 * ks;
                    ldsm4(ahi[mt], hi0 + boff);
                    ldsm4(alo[mt], lo0 + boff);
                }
                #pragma unroll
                for (int nfp = 0; nfp < 4; nfp++) {
                    uint4 f = sWf[ks * 512 + (32 * w + 8 * nfp + g) * 4 + t];
                    #pragma unroll
                    for (int mt = 0; mt < 2; mt++) {
                        mma_bf16(acc[mt][nfp], ahi[mt], f.x, f.y);   // hi*hi
                        mma_bf16(acc[mt][nfp], ahi[mt], f.z, f.w);   // hi*lo
                        mma_bf16(acc[mt][nfp], alo[mt], f.x, f.y);   // lo*hi
                    }
                }
            }
            bar_arrive(3 + s);           // stage free (acc in regs)

            // epilogue: c0,c1 -> row0+16mt+g ; c2,c3 -> +8 ; cols 32w+8nf'+2t
            #pragma unroll
            for (int mt = 0; mt < 2; mt++) {
                const int r0 = row0 + 16 * mt + g;
                #pragma unroll
                for (int nfp = 0; nfp < 4; nfp++) {
                    const int col = 32 * w + 8 * nfp + 2 * t;
                    float2 o0, o1;
                    o0.x = fmaxf(acc[mt][nfp][0] + bb[nfp].x, 0.f);
                    o0.y = fmaxf(acc[mt][nfp][1] + bb[nfp].y, 0.f);
                    o1.x = fmaxf(acc[mt][nfp][2] + bb[nfp].x, 0.f);
                    o1.y = fmaxf(acc[mt][nfp][3] + bb[nfp].y, 0.f);
                    *(float2*)(out + (size_t)r0 * C + col)       = o0;
                    *(float2*)(out + (size_t)(r0 + 8) * C + col) = o1;
                }
            }
        }
    }
}

extern "C" void kernel_launch(void* const* d_in, const int* in_sizes, int n_in,
                              void* d_out, int out_size)
{
    const float* x    = (const float*)d_in[0];
    const void*  ei   = d_in[1];
    const float* W    = (const float*)d_in[2];
    const float* bias = (const float*)d_in[3];
    const float* eps  = (const float*)d_in[4];
    float*       out  = (float*)d_out;

    cudaFuncSetAttribute(gin_fused_kernel,
                         cudaFuncAttributeMaxDynamicSharedMemorySize, SMEM_BYTES);

    gin_fused_kernel<<<GRID, THREADS, SMEM_BYTES>>>(x, ei, W, bias, eps, out);
}

// round 14
// speedup vs baseline: 1.4722x; 1.0204x over previous
#include <cuda_runtime.h>
#include <cuda_bf16.h>
#include <cstdint>

#define KNBR     16
#define C        128
#define ROWS     32768
#define TM       32              // rows per stage
#define THREADS  384             // warps 0-7 producer, 8-11 consumer
#define NTILES   (ROWS / TM)     // 1024
#define GRID     304             // 2 blocks/SM

// smem layout (bytes):
//   [0, 65536)             : sWf  — 4096 uint4 W-fragments, [ks][n][t]
//   [65536, +2*17408)      : 2 stages x (h_hi 8704 B + h_lo 8704 B)
//   [+, +8)                : per-stage tile slots
#define SWF_BYTES   65536
#define HSTRIDE_W   68           // u32 words per h row (136 bf16 = 272 B)
#define STAGE_U32   (TM * HSTRIDE_W)          // 2176 u32 per hi or lo array
#define STAGE_BYTES (2 * STAGE_U32 * 4)       // 17408
#define SMEM_BYTES  (SWF_BYTES + 2 * STAGE_BYTES + 8)

__device__ int g_tile_ctr;

typedef unsigned long long u64;

__device__ __forceinline__ u64 add2(u64 a, u64 b) {
    u64 d; asm("add.rn.f32x2 %0, %1, %2;" : "=l"(d) : "l"(a), "l"(b)); return d;
}
__device__ __forceinline__ u64 mul2(u64 a, u64 b) {
    u64 d; asm("mul.rn.f32x2 %0, %1, %2;" : "=l"(d) : "l"(a), "l"(b)); return d;
}
__device__ __forceinline__ u64 rep2(float v) {
    u64 d; asm("mov.b64 %0, {%1, %1};" : "=l"(d) : "f"(v)); return d;
}
__device__ __forceinline__ float2 unpack2(u64 v) {
    float2 r; asm("mov.b64 {%0, %1}, %2;" : "=f"(r.x), "=f"(r.y) : "l"(v)); return r;
}
__device__ __forceinline__ void hilo2(float a, float b, uint32_t& hi, uint32_t& lo) {
    __nv_bfloat162 h = __floats2bfloat162_rn(a, b);
    float ra = a - __bfloat162float(h.x);
    float rb = b - __bfloat162float(h.y);
    __nv_bfloat162 l = __floats2bfloat162_rn(ra, rb);
    hi = *reinterpret_cast<uint32_t*>(&h);
    lo = *reinterpret_cast<uint32_t*>(&l);
}
__device__ __forceinline__ void mma_bf16(float* c, const uint32_t* a, uint32_t b0, uint32_t b1) {
    asm volatile(
        "mma.sync.aligned.m16n8k16.row.col.f32.bf16.bf16.f32 "
        "{%0,%1,%2,%3}, {%4,%5,%6,%7}, {%8,%9}, {%0,%1,%2,%3};"
        : "+f"(c[0]), "+f"(c[1]), "+f"(c[2]), "+f"(c[3])
        : "r"(a[0]), "r"(a[1]), "r"(a[2]), "r"(a[3]), "r"(b0), "r"(b1));
}
__device__ __forceinline__ void ldsm4(uint32_t* r, uint32_t addr) {
    asm volatile("ldmatrix.sync.aligned.m8n8.x4.shared.b16 {%0,%1,%2,%3}, [%4];"
        : "=r"(r[0]), "=r"(r[1]), "=r"(r[2]), "=r"(r[3]) : "r"(addr));
}
__device__ __forceinline__ uint32_t smem_u32p(const void* p) {
    uint32_t a;
    asm("{ .reg .u64 t; cvta.to.shared.u64 t, %1; cvt.u32.u64 %0, t; }" : "=r"(a) : "l"(p));
    return a;
}
__device__ __forceinline__ void bar_sync(int id) {
    asm volatile("bar.sync %0, 384;" :: "r"(id) : "memory");
}
__device__ __forceinline__ void bar_arrive(int id) {
    asm volatile("bar.arrive %0, 384;" :: "r"(id) : "memory");
}
__device__ __forceinline__ void bar_sync_prod(int id) {     // producer-only (256 threads)
    asm volatile("bar.sync %0, 256;" :: "r"(id) : "memory");
}

__global__ void reset_ctr_kernel() { g_tile_ctr = 0; }

__global__ __launch_bounds__(THREADS, 2)
void gin_fused_kernel(const float* __restrict__ x,
                      const void* __restrict__ ei_raw,
                      const float* __restrict__ W,
                      const float* __restrict__ bias,
                      const float* __restrict__ epsp,
                      float* __restrict__ out)
{
    extern __shared__ char smem[];
    uint4*    sWf  = (uint4*)smem;                          // [ks][n][t]
    uint32_t* hbuf = (uint32_t*)(smem + SWF_BYTES);         // 2 stages x (hi | lo)
    volatile int* s_tile = (volatile int*)(smem + SWF_BYTES + 2 * STAGE_BYTES);

    const int tid = threadIdx.x;

    // ---------- dtype sniff: int64 (odd words all 0) vs int32 ----------
    const int* w32 = (const int*)ei_raw;
    int orv = 0;
    #pragma unroll
    for (int t = 0; t < 64; t++) orv |= w32[t * 8192 + 1];
    const bool is64 = (orv == 0);
    const long long* w64 = (const long long*)ei_raw;

    // ---------- build W fragments in smem: frag[ks*512 + n*4 + t] ----------
    for (int idx = tid; idx < 4096; idx += THREADS) {
        const int ks = idx >> 9;
        const int n  = (idx >> 2) & 127;
        const int t  = idx & 3;
        const int k0 = 16 * ks + 2 * t;
        const float* wr = W + (size_t)n * C;
        float2 wa = *(const float2*)(wr + k0);
        float2 wb = *(const float2*)(wr + k0 + 8);
        uint4 f;
        hilo2(wa.x, wa.y, f.x, f.z);
        hilo2(wb.x, wb.y, f.y, f.w);
        sWf[idx] = f;
    }
    __syncthreads();

    const float oe  = 1.0f + epsp[0];
    const u64   oe2 = rep2(oe);

    if (tid < 256) {
        // =================== PRODUCER: warps 0-7 ===================
        const int lrow = tid >> 3;        // 0..31 : row within tile
        const int p    = tid & 7;         // 16B slice of every 128B line

        for (int iter = 0;; iter++) {
            const int s = iter & 1;
            uint32_t* shi = hbuf + s * (2 * STAGE_U32);
            uint32_t* slo = shi + STAGE_U32;

            if (iter >= 2) bar_sync(3 + s);        // stage s consumed?

            if (tid == 0) s_tile[s] = atomicAdd(&g_tile_ctr, 1);
            bar_sync_prod(5);                      // broadcast tile to producers
            const int tile = s_tile[s];
            if (tile >= NTILES) { bar_arrive(1 + s); break; }

            const int row = tile * TM + lrow;
            const int bbase = (row >> 13) << 13;   // b * 8192

            int idxs[KNBR];
            if (!is64) {
                const int4* ip = (const int4*)(w32 + (size_t)row * KNBR);
                #pragma unroll
                for (int q = 0; q < 4; q++) {
                    int4 v = ip[q];
                    idxs[4*q+0] = v.x; idxs[4*q+1] = v.y;
                    idxs[4*q+2] = v.z; idxs[4*q+3] = v.w;
                }
            } else {
                #pragma unroll
                for (int k = 0; k < KNBR; k++)
                    idxs[k] = (int)w64[(size_t)row * KNBR + k];
            }
            #pragma unroll
            for (int k = 0; k < KNBR; k++)
                idxs[k] = (bbase + idxs[k]) << 7;

            const float* xs = x + ((size_t)row << 7) + 4 * p;
            u64 a[8];
            #pragma unroll
            for (int j = 0; j < 4; j++) {
                ulonglong2 v = *(const ulonglong2*)(xs + 32 * j);
                a[2*j]   = mul2(v.x, oe2);
                a[2*j+1] = mul2(v.y, oe2);
            }
            #pragma unroll 4
            for (int k = 0; k < KNBR; k++) {
                const float* xn = x + idxs[k] + 4 * p;
                #pragma unroll
                for (int j = 0; j < 4; j++) {
                    ulonglong2 v = *(const ulonglong2*)(xn + 32 * j);
                    a[2*j]   = add2(a[2*j],   v.x);
                    a[2*j+1] = add2(a[2*j+1], v.y);
                }
            }
            #pragma unroll
            for (int j = 0; j < 4; j++) {
                float2 f0 = unpack2(a[2*j]);
                float2 f1 = unpack2(a[2*j+1]);
                uint32_t h0, l0, h1, l1;
                hilo2(f0.x, f0.y, h0, l0);
                hilo2(f1.x, f1.y, h1, l1);
                const int wi = lrow * HSTRIDE_W + 16 * j + 2 * p;
                *(uint2*)(shi + wi) = make_uint2(h0, h1);
                *(uint2*)(slo + wi) = make_uint2(l0, l1);
            }
            bar_arrive(1 + s);           // stage s full
        }
    } else {
        // =================== CONSUMER: warps 8-11 ===================
        const int ct   = tid - 256;
        const int w    = ct >> 5;
        const int lane = ct & 31;
        const int g    = lane >> 2;
        const int t    = lane & 3;

        const int lrow  = (lane & 15);               // + 16*mt
        const int choff = ((lane >> 4) << 4);        // +8 bf16 for lanes 16-31
        const uint32_t hbase = smem_u32p(hbuf);

        float2 bb[4];
        #pragma unroll
        for (int nfp = 0; nfp < 4; nfp++)
            bb[nfp] = *(const float2*)(bias + 32 * w + 8 * nfp + 2 * t);

        for (int iter = 0;; iter++) {
            const int s = iter & 1;
            const uint32_t hi0 = hbase + s * (2 * STAGE_U32 * 4);
            const uint32_t lo0 = hi0 + STAGE_U32 * 4;

            bar_sync(1 + s);             // wait stage full
            const int tile = s_tile[s];
            if (tile >= NTILES) break;
            const int row0 = tile * TM;

            float acc[2][4][4];          // [mt][nf'][c]
            #pragma unroll
            for (int mt = 0; mt < 2; mt++)
                #pragma unroll
                for (int nfp = 0; nfp < 4; nfp++)
                    #pragma unroll
                    for (int q = 0; q < 4; q++) acc[mt][nfp][q] = 0.f;

            #pragma unroll
            for (int ks = 0; ks < 8; ks++) {
                uint32_t ahi[2][4], alo[2][4];
                #pragma unroll
                for (int mt = 0; mt < 2; mt++) {
                    const uint32_t boff =
                        (uint32_t)((16 * mt + lrow) * 272) + choff + 32 * ks;
                    ldsm4(ahi[mt], hi0 + boff);
                    ldsm4(alo[mt], lo0 + boff);
                }
                #pragma unroll
                for (int nfp = 0; nfp < 4; nfp++) {
                    uint4 f = sWf[ks * 512 + (32 * w + 8 * nfp + g) * 4 + t];
                    #pragma unroll
                    for (int mt = 0; mt < 2; mt++) {
                        mma_bf16(acc[mt][nfp], ahi[mt], f.x, f.y);   // hi*hi
                        mma_bf16(acc[mt][nfp], ahi[mt], f.z, f.w);   // hi*lo
                        mma_bf16(acc[mt][nfp], alo[mt], f.x, f.y);   // lo*hi
                    }
                }
            }
            bar_arrive(3 + s);           // stage free (acc in regs)

            #pragma unroll
            for (int mt = 0; mt < 2; mt++) {
                const int r0 = row0 + 16 * mt + g;
                #pragma unroll
                for (int nfp = 0; nfp < 4; nfp++) {
                    const int col = 32 * w + 8 * nfp + 2 * t;
                    float2 o0, o1;
                    o0.x = fmaxf(acc[mt][nfp][0] + bb[nfp].x, 0.f);
                    o0.y = fmaxf(acc[mt][nfp][1] + bb[nfp].y, 0.f);
                    o1.x = fmaxf(acc[mt][nfp][2] + bb[nfp].x, 0.f);
                    o1.y = fmaxf(acc[mt][nfp][3] + bb[nfp].y, 0.f);
                    *(float2*)(out + (size_t)r0 * C + col)       = o0;
                    *(float2*)(out + (size_t)(r0 + 8) * C + col) = o1;
                }
            }
        }
    }
}

extern "C" void kernel_launch(void* const* d_in, const int* in_sizes, int n_in,
                              void* d_out, int out_size)
{
    const float* x    = (const float*)d_in[0];
    const void*  ei   = d_in[1];
    const float* W    = (const float*)d_in[2];
    const float* bias = (const float*)d_in[3];
    const float* eps  = (const float*)d_in[4];
    float*       out  = (float*)d_out;

    cudaFuncSetAttribute(gin_fused_kernel,
                         cudaFuncAttributeMaxDynamicSharedMemorySize, SMEM_BYTES);

    reset_ctr_kernel<<<1, 1>>>();
    gin_fused_kernel<<<GRID, THREADS, SMEM_BYTES>>>(x, ei, W, bias, eps, out);
}

// round 15
// speedup vs baseline: 1.5492x; 1.0523x over previous
#include <cuda_runtime.h>
#include <cuda_bf16.h>
#include <cuda_fp16.h>
#include <cstdint>

#define KNBR     16
#define C        128
#define ROWS     32768
#define TM       32              // rows per stage
#define THREADS  384             // warps 0-7 producer, 8-11 consumer
#define NTILES   (ROWS / TM)     // 1024
#define GRID     304             // 2 blocks/SM

#define SWF_BYTES   65536
#define HSTRIDE_W   68           // u32 words per h row (136 bf16 = 272 B)
#define STAGE_U32   (TM * HSTRIDE_W)
#define STAGE_BYTES (2 * STAGE_U32 * 4)       // 17408
#define SMEM_BYTES  (SWF_BYTES + 2 * STAGE_BYTES + 8)

__device__ int   g_tile_ctr;
__device__ __half g_x16[ROWS * C];            // fp16 mirror of x (8 MB)

typedef unsigned long long u64;

__device__ __forceinline__ u64 add2(u64 a, u64 b) {
    u64 d; asm("add.rn.f32x2 %0, %1, %2;" : "=l"(d) : "l"(a), "l"(b)); return d;
}
__device__ __forceinline__ u64 mul2(u64 a, u64 b) {
    u64 d; asm("mul.rn.f32x2 %0, %1, %2;" : "=l"(d) : "l"(a), "l"(b)); return d;
}
__device__ __forceinline__ u64 rep2(float v) {
    u64 d; asm("mov.b64 %0, {%1, %1};" : "=l"(d) : "f"(v)); return d;
}
__device__ __forceinline__ u64 pack2(float a, float b) {
    u64 d; asm("mov.b64 %0, {%1, %2};" : "=l"(d) : "f"(a), "f"(b)); return d;
}
__device__ __forceinline__ float2 unpack2(u64 v) {
    float2 r; asm("mov.b64 {%0, %1}, %2;" : "=f"(r.x), "=f"(r.y) : "l"(v)); return r;
}
__device__ __forceinline__ u64 h2f2(uint32_t h) {
    __half2 hh = *reinterpret_cast<__half2*>(&h);
    float2 f = __half22float2(hh);
    return pack2(f.x, f.y);
}
__device__ __forceinline__ void hilo2(float a, float b, uint32_t& hi, uint32_t& lo) {
    __nv_bfloat162 h = __floats2bfloat162_rn(a, b);
    float ra = a - __bfloat162float(h.x);
    float rb = b - __bfloat162float(h.y);
    __nv_bfloat162 l = __floats2bfloat162_rn(ra, rb);
    hi = *reinterpret_cast<uint32_t*>(&h);
    lo = *reinterpret_cast<uint32_t*>(&l);
}
__device__ __forceinline__ void mma_bf16(float* c, const uint32_t* a, uint32_t b0, uint32_t b1) {
    asm volatile(
        "mma.sync.aligned.m16n8k16.row.col.f32.bf16.bf16.f32 "
        "{%0,%1,%2,%3}, {%4,%5,%6,%7}, {%8,%9}, {%0,%1,%2,%3};"
        : "+f"(c[0]), "+f"(c[1]), "+f"(c[2]), "+f"(c[3])
        : "r"(a[0]), "r"(a[1]), "r"(a[2]), "r"(a[3]), "r"(b0), "r"(b1));
}
__device__ __forceinline__ void ldsm4(uint32_t* r, uint32_t addr) {
    asm volatile("ldmatrix.sync.aligned.m8n8.x4.shared.b16 {%0,%1,%2,%3}, [%4];"
        : "=r"(r[0]), "=r"(r[1]), "=r"(r[2]), "=r"(r[3]) : "r"(addr));
}
__device__ __forceinline__ uint32_t smem_u32p(const void* p) {
    uint32_t a;
    asm("{ .reg .u64 t; cvta.to.shared.u64 t, %1; cvt.u32.u64 %0, t; }" : "=r"(a) : "l"(p));
    return a;
}
__device__ __forceinline__ void bar_sync(int id) {
    asm volatile("bar.sync %0, 384;" :: "r"(id) : "memory");
}
__device__ __forceinline__ void bar_arrive(int id) {
    asm volatile("bar.arrive %0, 384;" :: "r"(id) : "memory");
}
__device__ __forceinline__ void bar_sync_prod(int id) {
    asm volatile("bar.sync %0, 256;" :: "r"(id) : "memory");
}

// ---------- prologue: reset counter + convert x -> fp16 mirror ----------
__global__ void reset_ctr_kernel() { g_tile_ctr = 0; }

__global__ __launch_bounds__(256)
void cvt_x_kernel(const float* __restrict__ x)
{
    const int i = blockIdx.x * 256 + threadIdx.x;    // uint4 output index (8 halves)
    const float4* src = (const float4*)x;
    float4 a = src[2 * i], b = src[2 * i + 1];
    __half2 h0 = __floats2half2_rn(a.x, a.y);
    __half2 h1 = __floats2half2_rn(a.z, a.w);
    __half2 h2 = __floats2half2_rn(b.x, b.y);
    __half2 h3 = __floats2half2_rn(b.z, b.w);
    uint4 o;
    o.x = *reinterpret_cast<uint32_t*>(&h0);
    o.y = *reinterpret_cast<uint32_t*>(&h1);
    o.z = *reinterpret_cast<uint32_t*>(&h2);
    o.w = *reinterpret_cast<uint32_t*>(&h3);
    reinterpret_cast<uint4*>(g_x16)[i] = o;
}

__global__ __launch_bounds__(THREADS, 2)
void gin_fused_kernel(const float* __restrict__ x,
                      const void* __restrict__ ei_raw,
                      const float* __restrict__ W,
                      const float* __restrict__ bias,
                      const float* __restrict__ epsp,
                      float* __restrict__ out)
{
    extern __shared__ char smem[];
    uint4*    sWf  = (uint4*)smem;                          // [ks][n][t]
    uint32_t* hbuf = (uint32_t*)(smem + SWF_BYTES);         // 2 stages x (hi | lo)
    volatile int* s_tile = (volatile int*)(smem + SWF_BYTES + 2 * STAGE_BYTES);

    const int tid = threadIdx.x;

    // ---------- dtype sniff: int64 (odd words all 0) vs int32 ----------
    const int* w32 = (const int*)ei_raw;
    int orv = 0;
    #pragma unroll
    for (int t = 0; t < 64; t++) orv |= w32[t * 8192 + 1];
    const bool is64 = (orv == 0);
    const long long* w64 = (const long long*)ei_raw;

    // ---------- build W fragments in smem: frag[ks*512 + n*4 + t] ----------
    for (int idx = tid; idx < 4096; idx += THREADS) {
        const int ks = idx >> 9;
        const int n  = (idx >> 2) & 127;
        const int t  = idx & 3;
        const int k0 = 16 * ks + 2 * t;
        const float* wr = W + (size_t)n * C;
        float2 wa = *(const float2*)(wr + k0);
        float2 wb = *(const float2*)(wr + k0 + 8);
        uint4 f;
        hilo2(wa.x, wa.y, f.x, f.z);
        hilo2(wb.x, wb.y, f.y, f.w);
        sWf[idx] = f;
    }
    __syncthreads();

    const float oe  = 1.0f + epsp[0];
    const u64   oe2 = rep2(oe);

    if (tid < 256) {
        // =================== PRODUCER: warps 0-7 ===================
        // thread owns channels [8p, 8p+8) and [64+8p, 64+8p+8)
        const int lrow = tid >> 3;        // 0..31 : row within tile
        const int p    = tid & 7;

        for (int iter = 0;; iter++) {
            const int s = iter & 1;
            uint32_t* shi = hbuf + s * (2 * STAGE_U32);
            uint32_t* slo = shi + STAGE_U32;

            if (iter >= 2) bar_sync(3 + s);        // stage s consumed?

            if (tid == 0) s_tile[s] = atomicAdd(&g_tile_ctr, 1);
            bar_sync_prod(5);
            const int tile = s_tile[s];
            if (tile >= NTILES) { bar_arrive(1 + s); break; }

            const int row = tile * TM + lrow;
            const int bbase = (row >> 13) << 13;   // b * 8192

            int idxs[KNBR];
            if (!is64) {
                const int4* ip = (const int4*)(w32 + (size_t)row * KNBR);
                #pragma unroll
                for (int q = 0; q < 4; q++) {
                    int4 v = ip[q];
                    idxs[4*q+0] = v.x; idxs[4*q+1] = v.y;
                    idxs[4*q+2] = v.z; idxs[4*q+3] = v.w;
                }
            } else {
                #pragma unroll
                for (int k = 0; k < KNBR; k++)
                    idxs[k] = (int)w64[(size_t)row * KNBR + k];
            }
            #pragma unroll
            for (int k = 0; k < KNBR; k++)
                idxs[k] = (bbase + idxs[k]) << 7;  // element offset

            // self term (fp32): channels 8p.. and 64+8p..
            const float* xs = x + ((size_t)row << 7);
            u64 a[8];
            {
                float4 v0 = *(const float4*)(xs + 8 * p);
                float4 v1 = *(const float4*)(xs + 8 * p + 4);
                float4 v2 = *(const float4*)(xs + 64 + 8 * p);
                float4 v3 = *(const float4*)(xs + 64 + 8 * p + 4);
                a[0] = mul2(pack2(v0.x, v0.y), oe2);
                a[1] = mul2(pack2(v0.z, v0.w), oe2);
                a[2] = mul2(pack2(v1.x, v1.y), oe2);
                a[3] = mul2(pack2(v1.z, v1.w), oe2);
                a[4] = mul2(pack2(v2.x, v2.y), oe2);
                a[5] = mul2(pack2(v2.z, v2.w), oe2);
                a[6] = mul2(pack2(v3.x, v3.y), oe2);
                a[7] = mul2(pack2(v3.z, v3.w), oe2);
            }

            // neighbors from fp16 mirror: 2x LDG.128 per neighbor
            #pragma unroll 4
            for (int k = 0; k < KNBR; k++) {
                const __half* xn = g_x16 + idxs[k];
                uint4 v0 = *(const uint4*)(xn + 8 * p);
                uint4 v1 = *(const uint4*)(xn + 64 + 8 * p);
                a[0] = add2(a[0], h2f2(v0.x));
                a[1] = add2(a[1], h2f2(v0.y));
                a[2] = add2(a[2], h2f2(v0.z));
                a[3] = add2(a[3], h2f2(v0.w));
                a[4] = add2(a[4], h2f2(v1.x));
                a[5] = add2(a[5], h2f2(v1.y));
                a[6] = add2(a[6], h2f2(v1.z));
                a[7] = add2(a[7], h2f2(v1.w));
            }

            // convert to bf16 hi/lo words; word w holds channels 2w, 2w+1
            uint32_t hw[8], lw[8];
            #pragma unroll
            for (int q = 0; q < 8; q++) {
                float2 f = unpack2(a[q]);
                hilo2(f.x, f.y, hw[q], lw[q]);
            }
            const int wbase = lrow * HSTRIDE_W;
            *(uint4*)(shi + wbase + 4 * p)      = make_uint4(hw[0], hw[1], hw[2], hw[3]);
            *(uint4*)(shi + wbase + 32 + 4 * p) = make_uint4(hw[4], hw[5], hw[6], hw[7]);
            *(uint4*)(slo + wbase + 4 * p)      = make_uint4(lw[0], lw[1], lw[2], lw[3]);
            *(uint4*)(slo + wbase + 32 + 4 * p) = make_uint4(lw[4], lw[5], lw[6], lw[7]);

            bar_arrive(1 + s);           // stage s full
        }
    } else {
        // =================== CONSUMER: warps 8-11 (unchanged) ===================
        const int ct   = tid - 256;
        const int w    = ct >> 5;
        const int lane = ct & 31;
        const int g    = lane >> 2;
        const int t    = lane & 3;

        const int lrow  = (lane & 15);
        const int choff = ((lane >> 4) << 4);
        const uint32_t hbase = smem_u32p(hbuf);

        float2 bb[4];
        #pragma unroll
        for (int nfp = 0; nfp < 4; nfp++)
            bb[nfp] = *(const float2*)(bias + 32 * w + 8 * nfp + 2 * t);

        for (int iter = 0;; iter++) {
            const int s = iter & 1;
            const uint32_t hi0 = hbase + s * (2 * STAGE_U32 * 4);
            const uint32_t lo0 = hi0 + STAGE_U32 * 4;

            bar_sync(1 + s);
            const int tile = s_tile[s];
            if (tile >= NTILES) break;
            const int row0 = tile * TM;

            float acc[2][4][4];
            #pragma unroll
            for (int mt = 0; mt < 2; mt++)
                #pragma unroll
                for (int nfp = 0; nfp < 4; nfp++)
                    #pragma unroll
                    for (int q = 0; q < 4; q++) acc[mt][nfp][q] = 0.f;

            #pragma unroll
            for (int ks = 0; ks < 8; ks++) {
                uint32_t ahi[2][4], alo[2][4];
                #pragma unroll
                for (int mt = 0; mt < 2; mt++) {
                    const uint32_t boff =
                        (uint32_t)((16 * mt + lrow) * 272) + choff + 32 * ks;
                    ldsm4(ahi[mt], hi0 + boff);
                    ldsm4(alo[mt], lo0 + boff);
                }
                #pragma unroll
                for (int nfp = 0; nfp < 4; nfp++) {
                    uint4 f = sWf[ks * 512 + (32 * w + 8 * nfp + g) * 4 + t];
                    #pragma unroll
                    for (int mt = 0; mt < 2; mt++) {
                        mma_bf16(acc[mt][nfp], ahi[mt], f.x, f.y);
                        mma_bf16(acc[mt][nfp], ahi[mt], f.z, f.w);
                        mma_bf16(acc[mt][nfp], alo[mt], f.x, f.y);
                    }
                }
            }
            bar_arrive(3 + s);

            #pragma unroll
            for (int mt = 0; mt < 2; mt++) {
                const int r0 = row0 + 16 * mt + g;
                #pragma unroll
                for (int nfp = 0; nfp < 4; nfp++) {
                    const int col = 32 * w + 8 * nfp + 2 * t;
                    float2 o0, o1;
                    o0.x = fmaxf(acc[mt][nfp][0] + bb[nfp].x, 0.f);
                    o0.y = fmaxf(acc[mt][nfp][1] + bb[nfp].y, 0.f);
                    o1.x = fmaxf(acc[mt][nfp][2] + bb[nfp].x, 0.f);
                    o1.y = fmaxf(acc[mt][nfp][3] + bb[nfp].y, 0.f);
                    *(float2*)(out + (size_t)r0 * C + col)       = o0;
                    *(float2*)(out + (size_t)(r0 + 8) * C + col) = o1;
                }
            }
        }
    }
}

extern "C" void kernel_launch(void* const* d_in, const int* in_sizes, int n_in,
                              void* d_out, int out_size)
{
    const float* x    = (const float*)d_in[0];
    const void*  ei   = d_in[1];
    const float* W    = (const float*)d_in[2];
    const float* bias = (const float*)d_in[3];
    const float* eps  = (const float*)d_in[4];
    float*       out  = (float*)d_out;

    cudaFuncSetAttribute(gin_fused_kernel,
                         cudaFuncAttributeMaxDynamicSharedMemorySize, SMEM_BYTES);

    reset_ctr_kernel<<<1, 1>>>();
    cvt_x_kernel<<<ROWS * C / 8 / 256, 256>>>(x);   // x -> fp16 mirror
    gin_fused_kernel<<<GRID, THREADS, SMEM_BYTES>>>(x, ei, W, bias, eps, out);
}

// round 16
// speedup vs baseline: 1.6579x; 1.0702x over previous
#include <cuda_runtime.h>
#include <cuda_bf16.h>
#include <cuda_fp16.h>
#include <cstdint>

#define KNBR     16
#define C        128
#define ROWS     32768
#define TM       32              // rows per stage
#define THREADS  384             // warps 0-7 producer, 8-11 consumer
#define NTILES   (ROWS / TM)     // 1024
#define GRID     304             // 2 blocks/SM

#define SWF_BYTES   65536
#define HSTRIDE_W   68           // u32 words per h row (136 bf16 = 272 B)
#define STAGE_U32   (TM * HSTRIDE_W)
#define STAGE_BYTES (2 * STAGE_U32 * 4)       // 17408
#define SMEM_BYTES  (SWF_BYTES + 2 * STAGE_BYTES + 16)

__device__ int    g_tile_ctr;
__device__ __half g_x16[ROWS * C];            // fp16 mirror of x (8 MB)

typedef unsigned long long u64;

__device__ __forceinline__ u64 add2(u64 a, u64 b) {
    u64 d; asm("add.rn.f32x2 %0, %1, %2;" : "=l"(d) : "l"(a), "l"(b)); return d;
}
__device__ __forceinline__ u64 mul2(u64 a, u64 b) {
    u64 d; asm("mul.rn.f32x2 %0, %1, %2;" : "=l"(d) : "l"(a), "l"(b)); return d;
}
__device__ __forceinline__ u64 rep2(float v) {
    u64 d; asm("mov.b64 %0, {%1, %1};" : "=l"(d) : "f"(v)); return d;
}
__device__ __forceinline__ u64 pack2(float a, float b) {
    u64 d; asm("mov.b64 %0, {%1, %2};" : "=l"(d) : "f"(a), "f"(b)); return d;
}
__device__ __forceinline__ float2 unpack2(u64 v) {
    float2 r; asm("mov.b64 {%0, %1}, %2;" : "=f"(r.x), "=f"(r.y) : "l"(v)); return r;
}
__device__ __forceinline__ u64 h2f2(uint32_t h) {
    __half2 hh = *reinterpret_cast<__half2*>(&h);
    float2 f = __half22float2(hh);
    return pack2(f.x, f.y);
}
__device__ __forceinline__ void hilo2(float a, float b, uint32_t& hi, uint32_t& lo) {
    __nv_bfloat162 h = __floats2bfloat162_rn(a, b);
    float ra = a - __bfloat162float(h.x);
    float rb = b - __bfloat162float(h.y);
    __nv_bfloat162 l = __floats2bfloat162_rn(ra, rb);
    hi = *reinterpret_cast<uint32_t*>(&h);
    lo = *reinterpret_cast<uint32_t*>(&l);
}
__device__ __forceinline__ void mma_bf16(float* c, const uint32_t* a, uint32_t b0, uint32_t b1) {
    asm volatile(
        "mma.sync.aligned.m16n8k16.row.col.f32.bf16.bf16.f32 "
        "{%0,%1,%2,%3}, {%4,%5,%6,%7}, {%8,%9}, {%0,%1,%2,%3};"
        : "+f"(c[0]), "+f"(c[1]), "+f"(c[2]), "+f"(c[3])
        : "r"(a[0]), "r"(a[1]), "r"(a[2]), "r"(a[3]), "r"(b0), "r"(b1));
}
__device__ __forceinline__ void ldsm4(uint32_t* r, uint32_t addr) {
    asm volatile("ldmatrix.sync.aligned.m8n8.x4.shared.b16 {%0,%1,%2,%3}, [%4];"
        : "=r"(r[0]), "=r"(r[1]), "=r"(r[2]), "=r"(r[3]) : "r"(addr));
}
__device__ __forceinline__ uint32_t smem_u32p(const void* p) {
    uint32_t a;
    asm("{ .reg .u64 t; cvta.to.shared.u64 t, %1; cvt.u32.u64 %0, t; }" : "=r"(a) : "l"(p));
    return a;
}
__device__ __forceinline__ void bar_sync(int id) {
    asm volatile("bar.sync %0, 384;" :: "r"(id) : "memory");
}
__device__ __forceinline__ void bar_arrive(int id) {
    asm volatile("bar.arrive %0, 384;" :: "r"(id) : "memory");
}
__device__ __forceinline__ void bar_sync_prod(int id) {
    asm volatile("bar.sync %0, 256;" :: "r"(id) : "memory");
}

// ---------- prologue: convert x -> fp16 mirror + reset work counter ----------
__global__ __launch_bounds__(256)
void cvt_x_kernel(const float* __restrict__ x)
{
    const int i = blockIdx.x * 256 + threadIdx.x;    // uint4 output index (8 halves)
    if (i == 0) g_tile_ctr = 0;
    const float4* src = (const float4*)x;
    float4 a = src[2 * i], b = src[2 * i + 1];
    __half2 h0 = __floats2half2_rn(a.x, a.y);
    __half2 h1 = __floats2half2_rn(a.z, a.w);
    __half2 h2 = __floats2half2_rn(b.x, b.y);
    __half2 h3 = __floats2half2_rn(b.z, b.w);
    uint4 o;
    o.x = *reinterpret_cast<uint32_t*>(&h0);
    o.y = *reinterpret_cast<uint32_t*>(&h1);
    o.z = *reinterpret_cast<uint32_t*>(&h2);
    o.w = *reinterpret_cast<uint32_t*>(&h3);
    reinterpret_cast<uint4*>(g_x16)[i] = o;
}

__global__ __launch_bounds__(THREADS, 2)
void gin_fused_kernel(const float* __restrict__ x,
                      const void* __restrict__ ei_raw,
                      const float* __restrict__ W,
                      const float* __restrict__ bias,
                      const float* __restrict__ epsp,
                      float* __restrict__ out)
{
    extern __shared__ char smem[];
    uint4*    sWf  = (uint4*)smem;                          // [ks][n][t]
    uint32_t* hbuf = (uint32_t*)(smem + SWF_BYTES);         // 2 stages x (hi | lo)
    volatile int* s_tile = (volatile int*)(smem + SWF_BYTES + 2 * STAGE_BYTES); // 4 slots

    const int tid = threadIdx.x;

    // ---------- dtype sniff: int64 (odd words all 0) vs int32 ----------
    const int* w32 = (const int*)ei_raw;
    int orv = 0;
    #pragma unroll
    for (int t = 0; t < 64; t++) orv |= w32[t * 8192 + 1];
    const bool is64 = (orv == 0);
    const long long* w64 = (const long long*)ei_raw;

    // ---------- build W fragments in smem: frag[ks*512 + n*4 + t] ----------
    for (int idx = tid; idx < 4096; idx += THREADS) {
        const int ks = idx >> 9;
        const int n  = (idx >> 2) & 127;
        const int t  = idx & 3;
        const int k0 = 16 * ks + 2 * t;
        const float* wr = W + (size_t)n * C;
        float2 wa = *(const float2*)(wr + k0);
        float2 wb = *(const float2*)(wr + k0 + 8);
        uint4 f;
        hilo2(wa.x, wa.y, f.x, f.z);
        hilo2(wb.x, wb.y, f.y, f.w);
        sWf[idx] = f;
    }
    __syncthreads();

    const float oe  = 1.0f + epsp[0];
    const u64   oe2 = rep2(oe);

    if (tid < 256) {
        // =================== PRODUCER: warps 0-7 ===================
        // thread owns channels [8p, 8p+8) and [64+8p, 64+8p+8)
        const int lrow = tid >> 3;        // 0..31 : row within tile
        const int p    = tid & 7;

        for (int iter = 0;; iter++) {
            const int s    = iter & 1;
            const int slot = iter & 3;
            uint32_t* shi = hbuf + s * (2 * STAGE_U32);
            uint32_t* slo = shi + STAGE_U32;

            // fetch + broadcast tile id (slot rotation makes early write safe)
            if (tid == 0) s_tile[slot] = atomicAdd(&g_tile_ctr, 1);
            bar_sync_prod(5);
            const int tile = s_tile[slot];
            if (tile >= NTILES) { bar_arrive(1 + s); break; }

            const int row = tile * TM + lrow;
            const int bbase = (row >> 13) << 13;   // b * 8192

            // ---- ALL register work happens BEFORE the empty-wait ----
            int idxs[KNBR];
            if (!is64) {
                const int4* ip = (const int4*)(w32 + (size_t)row * KNBR);
                #pragma unroll
                for (int q = 0; q < 4; q++) {
                    int4 v = ip[q];
                    idxs[4*q+0] = v.x; idxs[4*q+1] = v.y;
                    idxs[4*q+2] = v.z; idxs[4*q+3] = v.w;
                }
            } else {
                #pragma unroll
                for (int k = 0; k < KNBR; k++)
                    idxs[k] = (int)w64[(size_t)row * KNBR + k];
            }
            #pragma unroll
            for (int k = 0; k < KNBR; k++)
                idxs[k] = (bbase + idxs[k]) << 7;  // element offset

            // self term (fp32)
            const float* xs = x + ((size_t)row << 7);
            u64 a[8];
            {
                float4 v0 = *(const float4*)(xs + 8 * p);
                float4 v1 = *(const float4*)(xs + 8 * p + 4);
                float4 v2 = *(const float4*)(xs + 64 + 8 * p);
                float4 v3 = *(const float4*)(xs + 64 + 8 * p + 4);
                a[0] = mul2(pack2(v0.x, v0.y), oe2);
                a[1] = mul2(pack2(v0.z, v0.w), oe2);
                a[2] = mul2(pack2(v1.x, v1.y), oe2);
                a[3] = mul2(pack2(v1.z, v1.w), oe2);
                a[4] = mul2(pack2(v2.x, v2.y), oe2);
                a[5] = mul2(pack2(v2.z, v2.w), oe2);
                a[6] = mul2(pack2(v3.x, v3.y), oe2);
                a[7] = mul2(pack2(v3.z, v3.w), oe2);
            }

            // neighbors from fp16 mirror: 2x LDG.128 per neighbor
            #pragma unroll 4
            for (int k = 0; k < KNBR; k++) {
                const __half* xn = g_x16 + idxs[k];
                uint4 v0 = *(const uint4*)(xn + 8 * p);
                uint4 v1 = *(const uint4*)(xn + 64 + 8 * p);
                a[0] = add2(a[0], h2f2(v0.x));
                a[1] = add2(a[1], h2f2(v0.y));
                a[2] = add2(a[2], h2f2(v0.z));
                a[3] = add2(a[3], h2f2(v0.w));
                a[4] = add2(a[4], h2f2(v1.x));
                a[5] = add2(a[5], h2f2(v1.y));
                a[6] = add2(a[6], h2f2(v1.z));
                a[7] = add2(a[7], h2f2(v1.w));
            }

            // convert to bf16 hi/lo words
            uint32_t hw[8], lw[8];
            #pragma unroll
            for (int q = 0; q < 8; q++) {
                float2 f = unpack2(a[q]);
                hilo2(f.x, f.y, hw[q], lw[q]);
            }

            // ---- only NOW wait for the buffer, then store ----
            if (iter >= 2) bar_sync(3 + s);        // stage s consumed?

            const int wbase = lrow * HSTRIDE_W;
            *(uint4*)(shi + wbase + 4 * p)      = make_uint4(hw[0], hw[1], hw[2], hw[3]);
            *(uint4*)(shi + wbase + 32 + 4 * p) = make_uint4(hw[4], hw[5], hw[6], hw[7]);
            *(uint4*)(slo + wbase + 4 * p)      = make_uint4(lw[0], lw[1], lw[2], lw[3]);
            *(uint4*)(slo + wbase + 32 + 4 * p) = make_uint4(lw[4], lw[5], lw[6], lw[7]);

            bar_arrive(1 + s);           // stage s full
        }
    } else {
        // =================== CONSUMER: warps 8-11 ===================
        const int ct   = tid - 256;
        const int w    = ct >> 5;
        const int lane = ct & 31;
        const int g    = lane >> 2;
        const int t    = lane & 3;

        const int lrow  = (lane & 15);
        const int choff = ((lane >> 4) << 4);
        const uint32_t hbase = smem_u32p(hbuf);

        float2 bb[4];
        #pragma unroll
        for (int nfp = 0; nfp < 4; nfp++)
            bb[nfp] = *(const float2*)(bias + 32 * w + 8 * nfp + 2 * t);

        for (int iter = 0;; iter++) {
            const int s    = iter & 1;
            const int slot = iter & 3;
            const uint32_t hi0 = hbase + s * (2 * STAGE_U32 * 4);
            const uint32_t lo0 = hi0 + STAGE_U32 * 4;

            bar_sync(1 + s);             // wait stage full
            const int tile = s_tile[slot];
            if (tile >= NTILES) break;
            const int row0 = tile * TM;

            float acc[2][4][4];
            #pragma unroll
            for (int mt = 0; mt < 2; mt++)
                #pragma unroll
                for (int nfp = 0; nfp < 4; nfp++)
                    #pragma unroll
                    for (int q = 0; q < 4; q++) acc[mt][nfp][q] = 0.f;

            #pragma unroll
            for (int ks = 0; ks < 8; ks++) {
                uint32_t ahi[2][4], alo[2][4];
                #pragma unroll
                for (int mt = 0; mt < 2; mt++) {
                    const uint32_t boff =
                        (uint32_t)((16 * mt + lrow) * 272) + choff + 32 * ks;
                    ldsm4(ahi[mt], hi0 + boff);
                    ldsm4(alo[mt], lo0 + boff);
                }
                #pragma unroll
                for (int nfp = 0; nfp < 4; nfp++) {
                    uint4 f = sWf[ks * 512 + (32 * w + 8 * nfp + g) * 4 + t];
                    #pragma unroll
                    for (int mt = 0; mt < 2; mt++) {
                        mma_bf16(acc[mt][nfp], ahi[mt], f.x, f.y);
                        mma_bf16(acc[mt][nfp], ahi[mt], f.z, f.w);
                        mma_bf16(acc[mt][nfp], alo[mt], f.x, f.y);
                    }
                }
            }
            bar_arrive(3 + s);           // stage free (acc in regs)

            #pragma unroll
            for (int mt = 0; mt < 2; mt++) {
                const int r0 = row0 + 16 * mt + g;
                #pragma unroll
                for (int nfp = 0; nfp < 4; nfp++) {
                    const int col = 32 * w + 8 * nfp + 2 * t;
                    float2 o0, o1;
                    o0.x = fmaxf(acc[mt][nfp][0] + bb[nfp].x, 0.f);
                    o0.y = fmaxf(acc[mt][nfp][1] + bb[nfp].y, 0.f);
                    o1.x = fmaxf(acc[mt][nfp][2] + bb[nfp].x, 0.f);
                    o1.y = fmaxf(acc[mt][nfp][3] + bb[nfp].y, 0.f);
                    *(float2*)(out + (size_t)r0 * C + col)       = o0;
                    *(float2*)(out + (size_t)(r0 + 8) * C + col) = o1;
                }
            }
        }
    }
}

extern "C" void kernel_launch(void* const* d_in, const int* in_sizes, int n_in,
                              void* d_out, int out_size)
{
    const float* x    = (const float*)d_in[0];
    const void*  ei   = d_in[1];
    const float* W    = (const float*)d_in[2];
    const float* bias = (const float*)d_in[3];
    const float* eps  = (const float*)d_in[4];
    float*       out  = (float*)d_out;

    cudaFuncSetAttribute(gin_fused_kernel,
                         cudaFuncAttributeMaxDynamicSharedMemorySize, SMEM_BYTES);

    cvt_x_kernel<<<ROWS * C / 8 / 256, 256>>>(x);   // x -> fp16 mirror (+ ctr reset)
    gin_fused_kernel<<<GRID, THREADS, SMEM_BYTES>>>(x, ei, W, bias, eps, out);
}